// round 2
// baseline (speedup 1.0000x reference)
#include <cuda_runtime.h>
#include <math.h>
#include <stdint.h>

#define NN 30000
#define NE 480000
#define FDIM 192
#define DX 64

// ---------------- scratch arenas (no allocs allowed) ----------------
// floats: x(N*256) hc(N*256) h(N*256) tl(N*64) tg(N*64) vx1 vx2 tx1 tx2 (4x N*64)
//         logit(E) dinv(N)
__device__ float g_farena[35200000];
// ints: src(E) dst(E) order(E) cnt(N+1) off(N+1) cur(N) degs(N) is64(1)
__device__ int   g_iarena[1600064];

// ---------------- graph build ----------------
__global__ void k_detect(const void* ei, int* is64) {
    const int* p = (const int*)ei;
    int zeros = 0;
    for (int i = 1; i < 256; i += 2) if (p[i] == 0) zeros++;
    *is64 = (zeros >= 120) ? 1 : 0;
}

// convert edge list + histogram in one pass
__global__ void k_convert_hist(const void* ei, int* src, int* dst,
                               int* cnt, int* degs, const int* is64) {
    int e = blockIdx.x * blockDim.x + threadIdx.x;
    if (e >= NE) return;
    int s, d;
    if (*is64) {
        const long long* p = (const long long*)ei;
        s = (int)p[e];
        d = (int)p[NE + e];
    } else {
        const int* p = (const int*)ei;
        s = p[e];
        d = p[NE + e];
    }
    src[e] = s;
    dst[e] = d;
    atomicAdd(&cnt[d], 1);
    atomicAdd(&degs[s], 1);
}

__global__ void k_zero_i(int* a, int n) {
    int i = blockIdx.x * blockDim.x + threadIdx.x;
    if (i < n) a[i] = 0;
}

// single block, 1024 threads: exclusive scan over NN counts -> off, plus
// cur[n]=off[n] and dinv[n]=rsqrt(deg) computed in the same pass.
__global__ void k_scan(const int* cnt, int* off, int* cur,
                       const int* degs, float* dinv) {
    __shared__ int sh[1024];
    __shared__ int carry;
    if (threadIdx.x == 0) carry = 0;
    __syncthreads();
    for (int base = 0; base < NN; base += 1024) {
        int i = base + threadIdx.x;
        int v = (i < NN) ? cnt[i] : 0;
        sh[threadIdx.x] = v;
        __syncthreads();
        for (int o = 1; o < 1024; o <<= 1) {
            int t = (threadIdx.x >= o) ? sh[threadIdx.x - o] : 0;
            __syncthreads();
            sh[threadIdx.x] += t;
            __syncthreads();
        }
        if (i < NN) {
            int o = carry + sh[threadIdx.x] - v;
            off[i] = o;
            cur[i] = o;
            int dg = degs[i];
            dinv[i] = (dg > 0) ? rsqrtf((float)dg) : 0.f;
        }
        __syncthreads();
        if (threadIdx.x == 0) carry += sh[1023];
        __syncthreads();
    }
    if (threadIdx.x == 0) off[NN] = carry;
}

__global__ void k_fill(const int* dst, int* cur, int* order) {
    int e = blockIdx.x * blockDim.x + threadIdx.x;
    if (e >= NE) return;
    int p = atomicAdd(&cur[dst[e]], 1);
    order[p] = e;
}

__global__ void k_sortseg(const int* off, int* order) {
    int n = blockIdx.x * blockDim.x + threadIdx.x;
    if (n >= NN) return;
    int b = off[n], e = off[n + 1];
    for (int i = b + 1; i < e; i++) {
        int v = order[i];
        int j = i - 1;
        while (j >= b && order[j] > v) { order[j + 1] = order[j]; j--; }
        order[j + 1] = v;
    }
}

// ---------------- GEMM: C[Nr x M] = A[Nr x K] @ B[K x M] ----------------
__global__ void __launch_bounds__(256)
k_gemm(const float* __restrict__ A, int lda,
       const float* __restrict__ B, int ldb,
       float* __restrict__ C, int ldc,
       int Nr, int K, int M) {
    __shared__ float sA[16][64];
    __shared__ float sB[16][64];
    int tx = threadIdx.x, ty = threadIdx.y;
    int tid = ty * 16 + tx;
    int brow = blockIdx.y * 64, bcol = blockIdx.x * 64;
    float acc[4][4] = {};
    for (int k0 = 0; k0 < K; k0 += 16) {
#pragma unroll
        for (int i = 0; i < 4; i++) {
            int idx = tid + i * 256;
            int r = idx >> 4, c = idx & 15;
            float v = 0.f;
            if (brow + r < Nr && k0 + c < K) v = A[(size_t)(brow + r) * lda + k0 + c];
            sA[c][r] = v;
        }
#pragma unroll
        for (int i = 0; i < 4; i++) {
            int idx = tid + i * 256;
            int r = idx >> 6, c = idx & 63;
            float v = 0.f;
            if (k0 + r < K && bcol + c < M) v = B[(size_t)(k0 + r) * ldb + bcol + c];
            sB[r][c] = v;
        }
        __syncthreads();
#pragma unroll
        for (int kk = 0; kk < 16; kk++) {
            float a[4], b[4];
#pragma unroll
            for (int i = 0; i < 4; i++) a[i] = sA[kk][ty * 4 + i];
#pragma unroll
            for (int j = 0; j < 4; j++) b[j] = sB[kk][tx * 4 + j];
#pragma unroll
            for (int i = 0; i < 4; i++)
#pragma unroll
                for (int j = 0; j < 4; j++)
                    acc[i][j] += a[i] * b[j];
        }
        __syncthreads();
    }
#pragma unroll
    for (int i = 0; i < 4; i++) {
        int r = brow + ty * 4 + i;
        if (r >= Nr) continue;
#pragma unroll
        for (int j = 0; j < 4; j++) {
            int c = bcol + tx * 4 + j;
            if (c < M) C[(size_t)r * ldc + c] = acc[i][j];
        }
    }
}

// ---------------- row-wise tanh + l2norm (in place), one warp per row --------
__global__ void __launch_bounds__(256)
k_tanh_norm(float* __restrict__ x, const float* __restrict__ b, int dim) {
    int w = (blockIdx.x * blockDim.x + threadIdx.x) >> 5;
    int lane = threadIdx.x & 31;
    if (w >= NN) return;
    float* row = x + (size_t)w * dim;
    float v[8];
    float ss = 0.f;
#pragma unroll
    for (int j = 0; j < 8; j++) {
        v[j] = 0.f;
        int c = lane + 32 * j;
        if (c < dim) {
            float t = tanhf(row[c] + b[c]);
            v[j] = t;
            ss += t * t;
        }
    }
#pragma unroll
    for (int o = 16; o; o >>= 1) ss += __shfl_xor_sync(~0u, ss, o);
    float sc = 1.f / fmaxf(sqrtf(ss), 1e-12f);
#pragma unroll
    for (int j = 0; j < 8; j++) {
        int c = lane + 32 * j;
        if (c < dim) row[c] = v[j] * sc;
    }
}

// ---------------- GAT layer: per-dst-node, one warp per node ----------------
// out = lrelu( l2norm( segsoftmax_scatter + bias ) )
template <int C>
__global__ void __launch_bounds__(128)
k_gat(const float* __restrict__ hc, const int* __restrict__ src,
      const int* __restrict__ off, const int* __restrict__ order,
      const float* __restrict__ dinv, float* __restrict__ logit,
      const float* __restrict__ bias, float* __restrict__ out, int dim) {
    int n = (blockIdx.x * blockDim.x + threadIdx.x) >> 5;
    int lane = threadIdx.x & 31;
    if (n >= NN) return;
    float hd[C];
#pragma unroll
    for (int j = 0; j < C; j++) {
        int c = lane + 32 * j;
        hd[j] = (c < dim) ? hc[(size_t)n * dim + c] : 0.f;
    }
    int b0 = off[n], b1 = off[n + 1];
    float m = -1e30f;
    for (int p = b0; p < b1; p++) {
        int s = src[order[p]];
        const float* hs = hc + (size_t)s * dim;
        float d = 0.f;
#pragma unroll
        for (int j = 0; j < C; j++) {
            int c = lane + 32 * j;
            if (c < dim) {
                float v = hs[c];
                v = (v > 0.f) ? v : 0.01f * v;   // leaky_relu(xj)
                d += hd[j] * v;
            }
        }
#pragma unroll
        for (int o = 16; o; o >>= 1) d += __shfl_xor_sync(~0u, d, o);
        float t = d * dinv[s];
        float gate = 1.f / (1.f + __expf(-t));
        float lg = d * gate;
        if (lane == 0) logit[p] = lg;
        m = fmaxf(m, lg);
    }
    float denom = 0.f;
    float acc[C];
#pragma unroll
    for (int j = 0; j < C; j++) acc[j] = 0.f;
    for (int p = b0; p < b1; p++) {
        int s = src[order[p]];
        float w = __expf(logit[p] - m);
        denom += w;
        const float* hs = hc + (size_t)s * dim;
#pragma unroll
        for (int j = 0; j < C; j++) {
            int c = lane + 32 * j;
            if (c < dim) acc[j] += w * hs[c];
        }
    }
    float inv = 1.f / (denom + 1e-16f);
    float val[C];
    float ss = 0.f;
#pragma unroll
    for (int j = 0; j < C; j++) {
        val[j] = 0.f;
        int c = lane + 32 * j;
        if (c < dim) {
            float v = acc[j] * inv + bias[c];
            val[j] = v;
            ss += v * v;
        }
    }
#pragma unroll
    for (int o = 16; o; o >>= 1) ss += __shfl_xor_sync(~0u, ss, o);
    float sc = 1.f / fmaxf(sqrtf(ss), 1e-12f);
#pragma unroll
    for (int j = 0; j < C; j++) {
        int c = lane + 32 * j;
        if (c < dim) {
            float v = val[j] * sc;
            out[(size_t)n * dim + c] = (v > 0.f) ? v : 0.01f * v;   // lrelu(gat)
        }
    }
}

// x1 = lrelu( tg + gb + lrelu(tl + lb) + id_emb )
__global__ void __launch_bounds__(256)
k_combine(const float* __restrict__ tg, const float* __restrict__ gb,
          const float* __restrict__ tl, const float* __restrict__ lb,
          const float* __restrict__ id, float* __restrict__ out) {
    int i = blockIdx.x * blockDim.x + threadIdx.x;
    if (i >= NN * DX) return;
    int c = i & 63;
    float xh = tl[i] + lb[c];
    xh = (xh > 0.f) ? xh : 0.01f * xh;
    xh += id[i];
    float v = tg[i] + gb[c] + xh;
    out[i] = (v > 0.f) ? v : 0.01f * v;
}

// output: [representation | v_rep | t_rep], each N x 128 with rows [x1|x2]
__global__ void __launch_bounds__(256)
k_final(const float* __restrict__ vx1, const float* __restrict__ vx2,
        const float* __restrict__ tx1, const float* __restrict__ tx2,
        float* __restrict__ out, int out_size) {
    int i = blockIdx.x * blockDim.x + threadIdx.x;
    if (i >= NN * DX) return;
    int n = i >> 6, c = i & 63;
    float a1 = vx1[i], a2 = vx2[i], b1 = tx1[i], b2 = tx2[i];
    size_t base = (size_t)n * 128;
    out[base + c]      = (a1 + b1) * 0.5f;
    out[base + 64 + c] = (a2 + b2) * 0.5f;
    if (out_size >= 2 * NN * 128) {
        out[(size_t)NN * 128 + base + c]      = a1;
        out[(size_t)NN * 128 + base + 64 + c] = a2;
    }
    if (out_size >= 3 * NN * 128) {
        out[(size_t)2 * NN * 128 + base + c]      = b1;
        out[(size_t)2 * NN * 128 + base + 64 + c] = b2;
    }
}

// ---------------- host side ----------------
static void run_branch(const float* feat, int fcol_off, int Fd, int L,
                       void* const* P, const float* idemb,
                       float* x, float* hc, float* h, float* tl, float* tg,
                       float* bx1, float* bx2,
                       int* src, int* off, int* order, float* dinv, float* logit) {
    const float* mlp_w = (const float*)P[0];
    const float* mlp_b = (const float*)P[1];
    const float* c1_w  = (const float*)P[2];
    const float* c1_b  = (const float*)P[3];
    const float* l1_w  = (const float*)P[4];
    const float* l1_b  = (const float*)P[5];
    const float* g1_w  = (const float*)P[6];
    const float* g1_b  = (const float*)P[7];
    const float* c2_w  = (const float*)P[8];
    const float* c2_b  = (const float*)P[9];
    const float* l2_w  = (const float*)P[10];
    const float* l2_b  = (const float*)P[11];
    const float* g2_w  = (const float*)P[12];
    const float* g2_b  = (const float*)P[13];

    dim3 t16(16, 16);
    int gemrow = (NN + 63) / 64;
    int warpN_grid = (NN * 32 + 255) / 256;   // warp-per-row kernels, block 256
    int gat_grid = (NN * 32 + 127) / 128;     // warp-per-node, block 128
    int ew_grid = (NN * DX + 255) / 256;

    // x = l2norm(tanh(feat_part @ mlp_w + b))
    k_gemm<<<dim3((L + 63) / 64, gemrow), t16>>>(feat + fcol_off, FDIM, mlp_w, L, x, L, NN, Fd, L);
    k_tanh_norm<<<warpN_grid, 256>>>(x, mlp_b, L);

    // GAT layer 1
    k_gemm<<<dim3((L + 63) / 64, gemrow), t16>>>(x, L, c1_w, L, hc, L, NN, L, L);
    if (L == 256)      k_gat<8><<<gat_grid, 128>>>(hc, src, off, order, dinv, logit, c1_b, h, L);
    else if (L == 100) k_gat<4><<<gat_grid, 128>>>(hc, src, off, order, dinv, logit, c1_b, h, L);
    else               k_gat<2><<<gat_grid, 128>>>(hc, src, off, order, dinv, logit, c1_b, h, L);

    k_gemm<<<dim3(1, gemrow), t16>>>(x, L, l1_w, DX, tl, DX, NN, L, DX);
    k_gemm<<<dim3(1, gemrow), t16>>>(h, L, g1_w, DX, tg, DX, NN, L, DX);
    k_combine<<<ew_grid, 256>>>(tg, g1_b, tl, l1_b, idemb, bx1);

    // GAT layer 2 (dim 64)
    k_gemm<<<dim3(1, gemrow), t16>>>(bx1, DX, c2_w, DX, hc, DX, NN, DX, DX);
    k_gat<2><<<gat_grid, 128>>>(hc, src, off, order, dinv, logit, c2_b, h, DX);

    k_gemm<<<dim3(1, gemrow), t16>>>(bx1, DX, l2_w, DX, tl, DX, NN, DX, DX);
    k_gemm<<<dim3(1, gemrow), t16>>>(h, DX, g2_w, DX, tg, DX, NN, DX, DX);
    k_combine<<<ew_grid, 256>>>(tg, g2_b, tl, l2_b, idemb, bx2);
}

extern "C" void kernel_launch(void* const* d_in, const int* in_sizes, int n_in,
                              void* d_out, int out_size) {
    static float* F = nullptr;
    static int*   I = nullptr;
    if (!F) {
        cudaGetSymbolAddress((void**)&F, g_farena);
        cudaGetSymbolAddress((void**)&I, g_iarena);
    }

    // float arena layout
    float* x     = F;
    float* hc    = F + 7680000;
    float* h     = F + 2 * 7680000;
    float* tl    = F + 3 * 7680000;
    float* tg    = tl + 1920000;
    float* vx1   = tg + 1920000;
    float* vx2   = vx1 + 1920000;
    float* tx1   = vx2 + 1920000;
    float* tx2   = tx1 + 1920000;
    float* logit = tx2 + 1920000;
    float* dinv  = logit + NE;

    // int arena layout
    int* src   = I;
    int* dst   = I + NE;
    int* order = I + 2 * NE;
    int* cnt   = I + 3 * NE;
    int* off   = cnt + (NN + 1);
    int* cur   = off + (NN + 1);
    int* degs  = cur + NN;
    int* is64  = degs + NN;

    const float* feat  = (const float*)d_in[0];
    const void*  ei    = d_in[1];
    const float* idemb = (const float*)d_in[2];

    // ---- graph build (every launch; no caching allowed) ----
    k_detect<<<1, 1>>>(ei, is64);
    k_zero_i<<<(NN + 256) / 256, 256>>>(cnt, NN + 1);
    k_zero_i<<<(NN + 255) / 256, 256>>>(degs, NN);
    k_convert_hist<<<(NE + 255) / 256, 256>>>(ei, src, dst, cnt, degs, is64);
    k_scan<<<1, 1024>>>(cnt, off, cur, degs, dinv);
    k_fill<<<(NE + 255) / 256, 256>>>(dst, cur, order);
    k_sortseg<<<(NN + 255) / 256, 256>>>(off, order);

    // ---- v branch: feat cols [0,128), lat 256 ----
    run_branch(feat, 0, 128, 256, d_in + 3, idemb,
               x, hc, h, tl, tg, vx1, vx2, src, off, order, dinv, logit);
    // ---- t branch: feat cols [128,192), lat 100 ----
    run_branch(feat, 128, 64, 100, d_in + 17, idemb,
               x, hc, h, tl, tg, tx1, tx2, src, off, order, dinv, logit);

    // ---- outputs ----
    k_final<<<(NN * DX + 255) / 256, 256>>>(vx1, vx2, tx1, tx2, (float*)d_out, out_size);
}

// round 3
// speedup vs baseline: 1.3669x; 1.3669x over previous
#include <cuda_runtime.h>
#include <math.h>
#include <stdint.h>

#define NN 30000
#define NE 480000
#define FDIM 192
#define DX 64

// ---------------- scratch arenas (no allocs allowed) ----------------
__device__ float g_farena[35200000];
// ints: src(E) dst(E) order(E) esrc(E) cnt(N+1) off(N+1) cur(N) degs(N) is64(1)
__device__ int   g_iarena[2080064];

// ---------------- graph build ----------------
__global__ void k_detect(const void* ei, int* is64) {
    const int* p = (const int*)ei;
    int zeros = 0;
    for (int i = 1; i < 256; i += 2) if (p[i] == 0) zeros++;
    *is64 = (zeros >= 120) ? 1 : 0;
}

__global__ void k_convert_hist(const void* ei, int* src, int* dst,
                               int* cnt, int* degs, const int* is64) {
    int e = blockIdx.x * blockDim.x + threadIdx.x;
    if (e >= NE) return;
    int s, d;
    if (*is64) {
        const long long* p = (const long long*)ei;
        s = (int)p[e];
        d = (int)p[NE + e];
    } else {
        const int* p = (const int*)ei;
        s = p[e];
        d = p[NE + e];
    }
    src[e] = s;
    dst[e] = d;
    atomicAdd(&cnt[d], 1);
    atomicAdd(&degs[s], 1);
}

__global__ void k_zero_i(int* a, int n) {
    int i = blockIdx.x * blockDim.x + threadIdx.x;
    if (i < n) a[i] = 0;
}

__global__ void k_scan(const int* cnt, int* off, int* cur,
                       const int* degs, float* dinv) {
    __shared__ int sh[1024];
    __shared__ int carry;
    if (threadIdx.x == 0) carry = 0;
    __syncthreads();
    for (int base = 0; base < NN; base += 1024) {
        int i = base + threadIdx.x;
        int v = (i < NN) ? cnt[i] : 0;
        sh[threadIdx.x] = v;
        __syncthreads();
        for (int o = 1; o < 1024; o <<= 1) {
            int t = (threadIdx.x >= o) ? sh[threadIdx.x - o] : 0;
            __syncthreads();
            sh[threadIdx.x] += t;
            __syncthreads();
        }
        if (i < NN) {
            int o = carry + sh[threadIdx.x] - v;
            off[i] = o;
            cur[i] = o;
            int dg = degs[i];
            dinv[i] = (dg > 0) ? rsqrtf((float)dg) : 0.f;
        }
        __syncthreads();
        if (threadIdx.x == 0) carry += sh[1023];
        __syncthreads();
    }
    if (threadIdx.x == 0) off[NN] = carry;
}

__global__ void k_fill(const int* dst, int* cur, int* order) {
    int e = blockIdx.x * blockDim.x + threadIdx.x;
    if (e >= NE) return;
    int p = atomicAdd(&cur[dst[e]], 1);
    order[p] = e;
}

__global__ void k_sortseg(const int* off, int* order) {
    int n = blockIdx.x * blockDim.x + threadIdx.x;
    if (n >= NN) return;
    int b = off[n], e = off[n + 1];
    for (int i = b + 1; i < e; i++) {
        int v = order[i];
        int j = i - 1;
        while (j >= b && order[j] > v) { order[j + 1] = order[j]; j--; }
        order[j + 1] = v;
    }
}

// esrc[p] = src[order[p]]  (precomputed once; reused by all 4 GAT layers)
__global__ void k_gather_src(const int* src, const int* order, int* esrc) {
    int p = blockIdx.x * blockDim.x + threadIdx.x;
    if (p < NE) esrc[p] = src[order[p]];
}

// ---------------- GEMM: C[Nr x M] = A[Nr x K] @ B[K x M] ----------------
// BM=128, BN=64, BK=16, 256 threads, 8x4 per thread.
// EPI==1: C := lrelu( acc + gb[c] + lrelu(tl+lb) + id )   (requires M<=64, ldc=64)
template <int EPI>
__global__ void __launch_bounds__(256)
k_gemm128(const float* __restrict__ A, int lda,
          const float* __restrict__ B, int ldb,
          float* __restrict__ C, int ldc,
          int Nr, int K, int M,
          const float* __restrict__ tl, const float* __restrict__ lb,
          const float* __restrict__ gb, const float* __restrict__ id) {
    __shared__ float sA[16][128];
    __shared__ float sB[16][64];
    int tid = threadIdx.x;
    int tx = tid & 15, ty = tid >> 4;
    int brow = blockIdx.y * 128, bcol = blockIdx.x * 64;
    float acc[8][4] = {};

    for (int k0 = 0; k0 < K; k0 += 16) {
        // load A tile: 128 rows x 16 k, 2 float4 per thread
#pragma unroll
        for (int it = 0; it < 2; it++) {
            int idx = tid + it * 256;
            int r = idx >> 2, kq = (idx & 3) * 4;
            float4 v = {0.f, 0.f, 0.f, 0.f};
            if (brow + r < Nr) {
                const float* ap = A + (size_t)(brow + r) * lda + k0 + kq;
                if (k0 + kq + 3 < K) {
                    v = *(const float4*)ap;
                } else {
                    if (k0 + kq + 0 < K) v.x = ap[0];
                    if (k0 + kq + 1 < K) v.y = ap[1];
                    if (k0 + kq + 2 < K) v.z = ap[2];
                    if (k0 + kq + 3 < K) v.w = ap[3];
                }
            }
            sA[kq + 0][r] = v.x;
            sA[kq + 1][r] = v.y;
            sA[kq + 2][r] = v.z;
            sA[kq + 3][r] = v.w;
        }
        // load B tile: 16 k x 64 cols, 1 float4 per thread
        {
            int kr = tid >> 4, cq = (tid & 15) * 4;
            float4 v = {0.f, 0.f, 0.f, 0.f};
            if (k0 + kr < K) {
                const float* bp = B + (size_t)(k0 + kr) * ldb + bcol + cq;
                if (bcol + cq + 3 < M) {
                    v = *(const float4*)bp;
                } else {
                    if (bcol + cq + 0 < M) v.x = bp[0];
                    if (bcol + cq + 1 < M) v.y = bp[1];
                    if (bcol + cq + 2 < M) v.z = bp[2];
                    if (bcol + cq + 3 < M) v.w = bp[3];
                }
            }
            *(float4*)&sB[kr][cq] = v;
        }
        __syncthreads();
#pragma unroll
        for (int kk = 0; kk < 16; kk++) {
            float a[8], b[4];
#pragma unroll
            for (int i = 0; i < 8; i++) a[i] = sA[kk][ty * 8 + i];
#pragma unroll
            for (int j = 0; j < 4; j++) b[j] = sB[kk][tx * 4 + j];
#pragma unroll
            for (int i = 0; i < 8; i++)
#pragma unroll
                for (int j = 0; j < 4; j++)
                    acc[i][j] += a[i] * b[j];
        }
        __syncthreads();
    }
#pragma unroll
    for (int i = 0; i < 8; i++) {
        int r = brow + ty * 8 + i;
        if (r >= Nr) continue;
#pragma unroll
        for (int j = 0; j < 4; j++) {
            int c = bcol + tx * 4 + j;
            if (c >= M) continue;
            if (EPI == 0) {
                C[(size_t)r * ldc + c] = acc[i][j];
            } else {
                size_t lin = (size_t)r * 64 + c;
                float xh = tl[lin] + lb[c];
                xh = (xh > 0.f) ? xh : 0.01f * xh;
                xh += id[lin];
                float v = acc[i][j] + gb[c] + xh;
                C[lin] = (v > 0.f) ? v : 0.01f * v;
            }
        }
    }
}

// ---------------- row-wise tanh + l2norm (in place), one warp per row --------
__global__ void __launch_bounds__(256)
k_tanh_norm(float* __restrict__ x, const float* __restrict__ b, int dim) {
    int w = (blockIdx.x * blockDim.x + threadIdx.x) >> 5;
    int lane = threadIdx.x & 31;
    if (w >= NN) return;
    float* row = x + (size_t)w * dim;
    float v[8];
    float ss = 0.f;
#pragma unroll
    for (int j = 0; j < 8; j++) {
        v[j] = 0.f;
        int c = lane + 32 * j;
        if (c < dim) {
            float t = tanhf(row[c] + b[c]);
            v[j] = t;
            ss += t * t;
        }
    }
#pragma unroll
    for (int o = 16; o; o >>= 1) ss += __shfl_xor_sync(~0u, ss, o);
    float sc = 1.f / fmaxf(sqrtf(ss), 1e-12f);
#pragma unroll
    for (int j = 0; j < 8; j++) {
        int c = lane + 32 * j;
        if (c < dim) row[c] = v[j] * sc;
    }
}

// ---------------- vector row load helpers ----------------
template <int VEC>
__device__ __forceinline__ void ldrow(const float* __restrict__ p, float* v) {
    if (VEC == 8) {
        float4 a = *(const float4*)p;
        float4 b = *(const float4*)(p + 4);
        v[0] = a.x; v[1] = a.y; v[2] = a.z; v[3] = a.w;
        v[4] = b.x; v[5] = b.y; v[6] = b.z; v[7] = b.w;
    } else if (VEC == 4) {
        float4 a = *(const float4*)p;
        v[0] = a.x; v[1] = a.y; v[2] = a.z; v[3] = a.w;
    } else {
        float2 a = *(const float2*)p;
        v[0] = a.x; v[1] = a.y;
    }
}

template <int VEC>
__device__ __forceinline__ void strow(float* __restrict__ p, const float* v) {
    if (VEC == 8) {
        *(float4*)p       = make_float4(v[0], v[1], v[2], v[3]);
        *(float4*)(p + 4) = make_float4(v[4], v[5], v[6], v[7]);
    } else if (VEC == 4) {
        *(float4*)p = make_float4(v[0], v[1], v[2], v[3]);
    } else {
        *(float2*)p = make_float2(v[0], v[1]);
    }
}

// ---------------- GAT layer: single-pass online softmax, warp per node -------
// out = lrelu( l2norm( softmax-weighted sum of h[src] + bias ) )
// lane handles VEC consecutive channels at c0 = lane*VEC (dim % VEC == 0 shapes)
template <int VEC>
__global__ void __launch_bounds__(128)
k_gat(const float* __restrict__ hc, const int* __restrict__ esrc,
      const int* __restrict__ off, const float* __restrict__ dinv,
      const float* __restrict__ bias, float* __restrict__ out, int dim) {
    int n = (blockIdx.x * blockDim.x + threadIdx.x) >> 5;
    int lane = threadIdx.x & 31;
    if (n >= NN) return;
    int c0 = lane * VEC;
    bool valid = c0 < dim;

    float hd[VEC];
#pragma unroll
    for (int j = 0; j < VEC; j++) hd[j] = 0.f;
    if (valid) ldrow<VEC>(hc + (size_t)n * dim + c0, hd);

    int b0 = off[n], b1 = off[n + 1];
    float m = -1e30f, denom = 0.f;
    float acc[VEC];
#pragma unroll
    for (int j = 0; j < VEC; j++) acc[j] = 0.f;

    for (int p = b0; p < b1; p++) {
        int s = esrc[p];
        float v[VEC];
#pragma unroll
        for (int j = 0; j < VEC; j++) v[j] = 0.f;
        if (valid) ldrow<VEC>(hc + (size_t)s * dim + c0, v);
        float d = 0.f;
#pragma unroll
        for (int j = 0; j < VEC; j++) {
            float lr = (v[j] > 0.f) ? v[j] : 0.01f * v[j];
            d += hd[j] * lr;
        }
#pragma unroll
        for (int o = 16; o; o >>= 1) d += __shfl_xor_sync(~0u, d, o);
        float t = d * dinv[s];
        float gate = 1.f / (1.f + __expf(-t));
        float lg = d * gate;
        if (lg > m) {
            float sc = __expf(m - lg);
            denom *= sc;
#pragma unroll
            for (int j = 0; j < VEC; j++) acc[j] *= sc;
            m = lg;
        }
        float w = __expf(lg - m);
        denom += w;
#pragma unroll
        for (int j = 0; j < VEC; j++) acc[j] += w * v[j];
    }

    float inv = 1.f / (denom + 1e-16f);
    float val[VEC];
    float ss = 0.f;
#pragma unroll
    for (int j = 0; j < VEC; j++) {
        val[j] = 0.f;
        if (valid) {
            float v = acc[j] * inv + bias[c0 + j];
            val[j] = v;
            ss += v * v;
        }
    }
#pragma unroll
    for (int o = 16; o; o >>= 1) ss += __shfl_xor_sync(~0u, ss, o);
    float sc = 1.f / fmaxf(sqrtf(ss), 1e-12f);
    if (valid) {
        float res[VEC];
#pragma unroll
        for (int j = 0; j < VEC; j++) {
            float v = val[j] * sc;
            res[j] = (v > 0.f) ? v : 0.01f * v;
        }
        strow<VEC>(out + (size_t)n * dim + c0, res);
    }
}

// output: [representation | v_rep | t_rep], each N x 128 with rows [x1|x2]
__global__ void __launch_bounds__(256)
k_final(const float* __restrict__ vx1, const float* __restrict__ vx2,
        const float* __restrict__ tx1, const float* __restrict__ tx2,
        float* __restrict__ out, int out_size) {
    int i = blockIdx.x * blockDim.x + threadIdx.x;
    if (i >= NN * DX) return;
    int n = i >> 6, c = i & 63;
    float a1 = vx1[i], a2 = vx2[i], b1 = tx1[i], b2 = tx2[i];
    size_t base = (size_t)n * 128;
    out[base + c]      = (a1 + b1) * 0.5f;
    out[base + 64 + c] = (a2 + b2) * 0.5f;
    if (out_size >= 2 * NN * 128) {
        out[(size_t)NN * 128 + base + c]      = a1;
        out[(size_t)NN * 128 + base + 64 + c] = a2;
    }
    if (out_size >= 3 * NN * 128) {
        out[(size_t)2 * NN * 128 + base + c]      = b1;
        out[(size_t)2 * NN * 128 + base + 64 + c] = b2;
    }
}

// ---------------- host side ----------------
static void run_branch(const float* feat, int fcol_off, int Fd, int L,
                       void* const* P, const float* idemb,
                       float* x, float* hc, float* h, float* tl,
                       float* bx1, float* bx2,
                       int* esrc, int* off, float* dinv) {
    const float* mlp_w = (const float*)P[0];
    const float* mlp_b = (const float*)P[1];
    const float* c1_w  = (const float*)P[2];
    const float* c1_b  = (const float*)P[3];
    const float* l1_w  = (const float*)P[4];
    const float* l1_b  = (const float*)P[5];
    const float* g1_w  = (const float*)P[6];
    const float* g1_b  = (const float*)P[7];
    const float* c2_w  = (const float*)P[8];
    const float* c2_b  = (const float*)P[9];
    const float* l2_w  = (const float*)P[10];
    const float* l2_b  = (const float*)P[11];
    const float* g2_w  = (const float*)P[12];
    const float* g2_b  = (const float*)P[13];

    dim3 blk(256);
    int gy = (NN + 127) / 128;
    int warpN_grid = (NN * 32 + 255) / 256;
    int gat_grid = (NN * 32 + 127) / 128;

    // x = l2norm(tanh(feat_part @ mlp_w + b))
    k_gemm128<0><<<dim3((L + 63) / 64, gy), blk>>>(feat + fcol_off, FDIM, mlp_w, L, x, L,
                                                   NN, Fd, L, nullptr, nullptr, nullptr, nullptr);
    k_tanh_norm<<<warpN_grid, 256>>>(x, mlp_b, L);

    // GAT layer 1
    k_gemm128<0><<<dim3((L + 63) / 64, gy), blk>>>(x, L, c1_w, L, hc, L,
                                                   NN, L, L, nullptr, nullptr, nullptr, nullptr);
    if (L == 256)      k_gat<8><<<gat_grid, 128>>>(hc, esrc, off, dinv, c1_b, h, L);
    else if (L == 100) k_gat<4><<<gat_grid, 128>>>(hc, esrc, off, dinv, c1_b, h, L);
    else               k_gat<2><<<gat_grid, 128>>>(hc, esrc, off, dinv, c1_b, h, L);

    // x1 = lrelu( h@g1 + g1_b + lrelu(x@l1 + l1_b) + id )
    k_gemm128<0><<<dim3(1, gy), blk>>>(x, L, l1_w, DX, tl, DX,
                                       NN, L, DX, nullptr, nullptr, nullptr, nullptr);
    k_gemm128<1><<<dim3(1, gy), blk>>>(h, L, g1_w, DX, bx1, DX,
                                       NN, L, DX, tl, l1_b, g1_b, idemb);

    // GAT layer 2 (dim 64)
    k_gemm128<0><<<dim3(1, gy), blk>>>(bx1, DX, c2_w, DX, hc, DX,
                                       NN, DX, DX, nullptr, nullptr, nullptr, nullptr);
    k_gat<2><<<gat_grid, 128>>>(hc, esrc, off, dinv, c2_b, h, DX);

    k_gemm128<0><<<dim3(1, gy), blk>>>(bx1, DX, l2_w, DX, tl, DX,
                                       NN, DX, DX, nullptr, nullptr, nullptr, nullptr);
    k_gemm128<1><<<dim3(1, gy), blk>>>(h, DX, g2_w, DX, bx2, DX,
                                       NN, DX, DX, tl, l2_b, g2_b, idemb);
}

extern "C" void kernel_launch(void* const* d_in, const int* in_sizes, int n_in,
                              void* d_out, int out_size) {
    static float* F = nullptr;
    static int*   I = nullptr;
    if (!F) {
        cudaGetSymbolAddress((void**)&F, g_farena);
        cudaGetSymbolAddress((void**)&I, g_iarena);
    }

    // float arena layout
    float* x     = F;
    float* hc    = F + 7680000;
    float* h     = F + 2 * 7680000;
    float* tl    = F + 3 * 7680000;
    float* vx1   = tl + 1920000;
    float* vx2   = vx1 + 1920000;
    float* tx1   = vx2 + 1920000;
    float* tx2   = tx1 + 1920000;
    float* dinv  = tx2 + 1920000;

    // int arena layout
    int* src   = I;
    int* dst   = I + NE;
    int* order = I + 2 * NE;
    int* esrc  = I + 3 * NE;
    int* cnt   = I + 4 * NE;
    int* off   = cnt + (NN + 1);
    int* cur   = off + (NN + 1);
    int* degs  = cur + NN;
    int* is64  = degs + NN;

    const float* feat  = (const float*)d_in[0];
    const void*  ei    = d_in[1];
    const float* idemb = (const float*)d_in[2];

    // ---- graph build (every launch; no caching allowed) ----
    k_detect<<<1, 1>>>(ei, is64);
    k_zero_i<<<(NN + 256) / 256, 256>>>(cnt, NN + 1);
    k_zero_i<<<(NN + 255) / 256, 256>>>(degs, NN);
    k_convert_hist<<<(NE + 255) / 256, 256>>>(ei, src, dst, cnt, degs, is64);
    k_scan<<<1, 1024>>>(cnt, off, cur, degs, dinv);
    k_fill<<<(NE + 255) / 256, 256>>>(dst, cur, order);
    k_sortseg<<<(NN + 255) / 256, 256>>>(off, order);
    k_gather_src<<<(NE + 255) / 256, 256>>>(src, order, esrc);

    // ---- v branch: feat cols [0,128), lat 256 ----
    run_branch(feat, 0, 128, 256, d_in + 3, idemb,
               x, hc, h, tl, vx1, vx2, esrc, off, dinv);
    // ---- t branch: feat cols [128,192), lat 100 ----
    run_branch(feat, 128, 64, 100, d_in + 17, idemb,
               x, hc, h, tl, tx1, tx2, esrc, off, dinv);

    // ---- outputs ----
    k_final<<<(NN * DX + 255) / 256, 256>>>(vx1, vx2, tx1, tx2, (float*)d_out, out_size);
}

// round 4
// speedup vs baseline: 1.5764x; 1.1533x over previous
#include <cuda_runtime.h>
#include <math.h>
#include <stdint.h>

#define NN 30000
#define NE 480000
#define FDIM 192
#define DX 64
#define LV 256
#define LT 100

// ---------------- scratch arenas (no allocs allowed) ----------------
__device__ float g_farena[44000000];
__device__ int   g_iarena[2100000];

// ---------------- graph build ----------------
__global__ void k_detect(const void* ei, int* is64) {
    const int* p = (const int*)ei;
    int zeros = 0;
    for (int i = 1; i < 256; i += 2) if (p[i] == 0) zeros++;
    *is64 = (zeros >= 120) ? 1 : 0;
}

__global__ void k_zero_i(int* a, int n) {
    int i = blockIdx.x * blockDim.x + threadIdx.x;
    if (i < n) a[i] = 0;
}

__global__ void k_convert_hist(const void* ei, int* src, int* dst,
                               int* cnt, int* degs, const int* is64) {
    int e = blockIdx.x * blockDim.x + threadIdx.x;
    if (e >= NE) return;
    int s, d;
    if (*is64) {
        const long long* p = (const long long*)ei;
        s = (int)p[e];
        d = (int)p[NE + e];
    } else {
        const int* p = (const int*)ei;
        s = p[e];
        d = p[NE + e];
    }
    src[e] = s;
    dst[e] = d;
    atomicAdd(&cnt[d], 1);
    atomicAdd(&degs[s], 1);
}

// 1024 threads, 30 counts per thread serially + warp-shuffle hierarchical scan
__global__ void __launch_bounds__(1024)
k_scan(const int* __restrict__ cnt, int* __restrict__ off, int* __restrict__ cur,
       const int* __restrict__ degs, float* __restrict__ dinv) {
    const int CH = 30;  // 1024*30 = 30720 >= NN
    int t = threadIdx.x;
    int base = t * CH;
    int s = 0;
#pragma unroll 5
    for (int i = 0; i < CH; i++) {
        int idx = base + i;
        if (idx < NN) s += cnt[idx];
    }
    int lane = t & 31, wid = t >> 5;
    int v = s;
#pragma unroll
    for (int o = 1; o < 32; o <<= 1) {
        int u = __shfl_up_sync(~0u, v, o);
        if (lane >= o) v += u;
    }
    __shared__ int wt[32];
    if (lane == 31) wt[wid] = v;
    __syncthreads();
    if (wid == 0) {
        int w = wt[lane];
#pragma unroll
        for (int o = 1; o < 32; o <<= 1) {
            int u = __shfl_up_sync(~0u, w, o);
            if (lane >= o) w += u;
        }
        wt[lane] = w;
    }
    __syncthreads();
    int pre = v - s + (wid ? wt[wid - 1] : 0);
    int run = pre;
#pragma unroll 5
    for (int i = 0; i < CH; i++) {
        int idx = base + i;
        if (idx < NN) {
            off[idx] = run;
            cur[idx] = run;
            int dg = degs[idx];
            dinv[idx] = (dg > 0) ? rsqrtf((float)dg) : 0.f;
            run += cnt[idx];
        }
    }
    if (t == 1023) off[NN] = run;
}

__global__ void k_fill(const int* dst, int* cur, int* order) {
    int e = blockIdx.x * blockDim.x + threadIdx.x;
    if (e >= NE) return;
    int p = atomicAdd(&cur[dst[e]], 1);
    order[p] = e;
}

// per-node insertion sort for determinism, then esrc[p] = src[order[p]]
__global__ void k_sortseg_gather(const int* __restrict__ off, int* __restrict__ order,
                                 const int* __restrict__ src, int* __restrict__ esrc) {
    int n = blockIdx.x * blockDim.x + threadIdx.x;
    if (n >= NN) return;
    int b = off[n], e = off[n + 1];
    for (int i = b + 1; i < e; i++) {
        int v = order[i];
        int j = i - 1;
        while (j >= b && order[j] > v) { order[j + 1] = order[j]; j--; }
        order[j + 1] = v;
    }
    for (int p = b; p < e; p++) esrc[p] = src[order[p]];
}

// ---------------- combined two-branch GEMM ----------------
struct GP {
    const float* A;
    const float* B;
    float* C;
    const float* tl;
    const float* lb;
    const float* gb;
    int lda, ldb, ldc, K, M;
};

// BM=128, BN=64, BK=16, 256 threads, 8x4 per thread. blockIdx.z selects branch.
// EPI==1: C := lrelu( acc + gb[c] + lrelu(tl+lb) + id )  (M<=64, ldc=64)
template <int EPI>
__global__ void __launch_bounds__(256)
k_gemm2(GP g0, GP g1, const float* __restrict__ id) {
    GP g = (blockIdx.z == 0) ? g0 : g1;
    int bcol = blockIdx.x * 64;
    if (bcol >= g.M) return;
    __shared__ float sA[16][128];
    __shared__ float sB[16][64];
    int tid = threadIdx.x;
    int tx = tid & 15, ty = tid >> 4;
    int brow = blockIdx.y * 128;
    const int K = g.K, M = g.M;
    float acc[8][4] = {};

    for (int k0 = 0; k0 < K; k0 += 16) {
#pragma unroll
        for (int it = 0; it < 2; it++) {
            int idx = tid + it * 256;
            int r = idx >> 2, kq = (idx & 3) * 4;
            float4 v = {0.f, 0.f, 0.f, 0.f};
            if (brow + r < NN) {
                const float* ap = g.A + (size_t)(brow + r) * g.lda + k0 + kq;
                if (k0 + kq + 3 < K) {
                    v = *(const float4*)ap;
                } else {
                    if (k0 + kq + 0 < K) v.x = ap[0];
                    if (k0 + kq + 1 < K) v.y = ap[1];
                    if (k0 + kq + 2 < K) v.z = ap[2];
                    if (k0 + kq + 3 < K) v.w = ap[3];
                }
            }
            sA[kq + 0][r] = v.x;
            sA[kq + 1][r] = v.y;
            sA[kq + 2][r] = v.z;
            sA[kq + 3][r] = v.w;
        }
        {
            int kr = tid >> 4, cq = (tid & 15) * 4;
            float4 v = {0.f, 0.f, 0.f, 0.f};
            if (k0 + kr < K) {
                const float* bp = g.B + (size_t)(k0 + kr) * g.ldb + bcol + cq;
                if (bcol + cq + 3 < M) {
                    v = *(const float4*)bp;
                } else {
                    if (bcol + cq + 0 < M) v.x = bp[0];
                    if (bcol + cq + 1 < M) v.y = bp[1];
                    if (bcol + cq + 2 < M) v.z = bp[2];
                    if (bcol + cq + 3 < M) v.w = bp[3];
                }
            }
            *(float4*)&sB[kr][cq] = v;
        }
        __syncthreads();
#pragma unroll
        for (int kk = 0; kk < 16; kk++) {
            float a[8], b[4];
#pragma unroll
            for (int i = 0; i < 8; i++) a[i] = sA[kk][ty * 8 + i];
#pragma unroll
            for (int j = 0; j < 4; j++) b[j] = sB[kk][tx * 4 + j];
#pragma unroll
            for (int i = 0; i < 8; i++)
#pragma unroll
                for (int j = 0; j < 4; j++)
                    acc[i][j] += a[i] * b[j];
        }
        __syncthreads();
    }
#pragma unroll
    for (int i = 0; i < 8; i++) {
        int r = brow + ty * 8 + i;
        if (r >= NN) continue;
#pragma unroll
        for (int j = 0; j < 4; j++) {
            int c = bcol + tx * 4 + j;
            if (c >= M) continue;
            if (EPI == 0) {
                g.C[(size_t)r * g.ldc + c] = acc[i][j];
            } else {
                size_t lin = (size_t)r * 64 + c;
                float xh = g.tl[lin] + g.lb[c];
                xh = (xh > 0.f) ? xh : 0.01f * xh;
                xh += id[lin];
                float v = acc[i][j] + g.gb[c] + xh;
                g.C[lin] = (v > 0.f) ? v : 0.01f * v;
            }
        }
    }
}

// ---------------- combined tanh + l2norm (both branches) ----------------
__global__ void __launch_bounds__(256)
k_tanh2(float* __restrict__ xv, const float* __restrict__ bv,
        float* __restrict__ xt, const float* __restrict__ bt) {
    int w = (blockIdx.x * blockDim.x + threadIdx.x) >> 5;
    int lane = threadIdx.x & 31;
    if (w >= 2 * NN) return;
    float* row;
    const float* b;
    int dim;
    if (w < NN) { row = xv + (size_t)w * LV; b = bv; dim = LV; }
    else        { row = xt + (size_t)(w - NN) * LT; b = bt; dim = LT; }
    float v[8];
    float ss = 0.f;
#pragma unroll
    for (int j = 0; j < 8; j++) {
        v[j] = 0.f;
        int c = lane + 32 * j;
        if (c < dim) {
            float t = tanhf(row[c] + b[c]);
            v[j] = t;
            ss += t * t;
        }
    }
#pragma unroll
    for (int o = 16; o; o >>= 1) ss += __shfl_xor_sync(~0u, ss, o);
    float sc = 1.f / fmaxf(sqrtf(ss), 1e-12f);
#pragma unroll
    for (int j = 0; j < 8; j++) {
        int c = lane + 32 * j;
        if (c < dim) row[c] = v[j] * sc;
    }
}

// ---------------- vector helpers ----------------
template <int VEC>
__device__ __forceinline__ void ldrow(const float* __restrict__ p, float* v) {
    if (VEC == 8) {
        float4 a = *(const float4*)p;
        float4 b = *(const float4*)(p + 4);
        v[0] = a.x; v[1] = a.y; v[2] = a.z; v[3] = a.w;
        v[4] = b.x; v[5] = b.y; v[6] = b.z; v[7] = b.w;
    } else if (VEC == 4) {
        float4 a = *(const float4*)p;
        v[0] = a.x; v[1] = a.y; v[2] = a.z; v[3] = a.w;
    } else {
        float2 a = *(const float2*)p;
        v[0] = a.x; v[1] = a.y;
    }
}

template <int VEC>
__device__ __forceinline__ void strow(float* __restrict__ p, const float* v) {
    if (VEC == 8) {
        *(float4*)p       = make_float4(v[0], v[1], v[2], v[3]);
        *(float4*)(p + 4) = make_float4(v[4], v[5], v[6], v[7]);
    } else if (VEC == 4) {
        *(float4*)p = make_float4(v[0], v[1], v[2], v[3]);
    } else {
        *(float2*)p = make_float2(v[0], v[1]);
    }
}

// ---------------- GAT (single-pass online softmax) ----------------
template <int VEC>
__device__ __forceinline__ void gat_update(const float* v, float di,
                                           const float (&hd)[VEC], float (&acc)[VEC],
                                           float& m, float& denom) {
    float d = 0.f;
#pragma unroll
    for (int j = 0; j < VEC; j++) {
        float lr = (v[j] > 0.f) ? v[j] : 0.01f * v[j];
        d += hd[j] * lr;
    }
#pragma unroll
    for (int o = 16; o; o >>= 1) d += __shfl_xor_sync(~0u, d, o);
    float t = d * di;
    float gate = 1.f / (1.f + __expf(-t));
    float lg = d * gate;
    if (lg > m) {
        float sc = __expf(m - lg);
        denom *= sc;
#pragma unroll
        for (int j = 0; j < VEC; j++) acc[j] *= sc;
        m = lg;
    }
    float w = __expf(lg - m);
    denom += w;
#pragma unroll
    for (int j = 0; j < VEC; j++) acc[j] += w * v[j];
}

template <int VEC>
__device__ __forceinline__ void gat_node(const float* __restrict__ hc, int dim,
                                         const int* __restrict__ esrc, int b0, int b1,
                                         const float* __restrict__ dinv,
                                         const float* __restrict__ bias,
                                         float* __restrict__ out, int n, int lane) {
    int c0 = lane * VEC;
    bool valid = c0 < dim;
    float hd[VEC];
#pragma unroll
    for (int j = 0; j < VEC; j++) hd[j] = 0.f;
    if (valid) ldrow<VEC>(hc + (size_t)n * dim + c0, hd);

    float m = -1e30f, denom = 0.f;
    float acc[VEC];
#pragma unroll
    for (int j = 0; j < VEC; j++) acc[j] = 0.f;

    int p = b0;
    for (; p + 1 < b1; p += 2) {
        int s0 = esrc[p], s1 = esrc[p + 1];
        float di0 = dinv[s0], di1 = dinv[s1];
        float v0[VEC], v1[VEC];
#pragma unroll
        for (int j = 0; j < VEC; j++) { v0[j] = 0.f; v1[j] = 0.f; }
        if (valid) {
            ldrow<VEC>(hc + (size_t)s0 * dim + c0, v0);
            ldrow<VEC>(hc + (size_t)s1 * dim + c0, v1);
        }
        gat_update<VEC>(v0, di0, hd, acc, m, denom);
        gat_update<VEC>(v1, di1, hd, acc, m, denom);
    }
    if (p < b1) {
        int s = esrc[p];
        float di = dinv[s];
        float v[VEC];
#pragma unroll
        for (int j = 0; j < VEC; j++) v[j] = 0.f;
        if (valid) ldrow<VEC>(hc + (size_t)s * dim + c0, v);
        gat_update<VEC>(v, di, hd, acc, m, denom);
    }

    float inv = 1.f / (denom + 1e-16f);
    float val[VEC];
    float ss = 0.f;
#pragma unroll
    for (int j = 0; j < VEC; j++) {
        val[j] = 0.f;
        if (valid) {
            float v = acc[j] * inv + bias[c0 + j];
            val[j] = v;
            ss += v * v;
        }
    }
#pragma unroll
    for (int o = 16; o; o >>= 1) ss += __shfl_xor_sync(~0u, ss, o);
    float sc = 1.f / fmaxf(sqrtf(ss), 1e-12f);
    if (valid) {
        float res[VEC];
#pragma unroll
        for (int j = 0; j < VEC; j++) {
            float v = val[j] * sc;
            res[j] = (v > 0.f) ? v : 0.01f * v;
        }
        strow<VEC>(out + (size_t)n * dim + c0, res);
    }
}

// layer 1: v dim=256 (VEC=8), t dim=100 (VEC=4)
__global__ void __launch_bounds__(128)
k_gat1(const float* __restrict__ hcv, const float* __restrict__ hct,
       const int* __restrict__ esrc, const int* __restrict__ off,
       const float* __restrict__ dinv,
       const float* __restrict__ bv, const float* __restrict__ bt,
       float* __restrict__ ov, float* __restrict__ ot) {
    int w = (blockIdx.x * blockDim.x + threadIdx.x) >> 5;
    int lane = threadIdx.x & 31;
    if (w >= 2 * NN) return;
    if (w < NN) {
        gat_node<8>(hcv, LV, esrc, off[w], off[w + 1], dinv, bv, ov, w, lane);
    } else {
        int n = w - NN;
        gat_node<4>(hct, LT, esrc, off[n], off[n + 1], dinv, bt, ot, n, lane);
    }
}

// layer 2: both branches dim=64 (VEC=2)
__global__ void __launch_bounds__(128)
k_gat2(const float* __restrict__ hcv, const float* __restrict__ hct,
       const int* __restrict__ esrc, const int* __restrict__ off,
       const float* __restrict__ dinv,
       const float* __restrict__ bv, const float* __restrict__ bt,
       float* __restrict__ ov, float* __restrict__ ot) {
    int w = (blockIdx.x * blockDim.x + threadIdx.x) >> 5;
    int lane = threadIdx.x & 31;
    if (w >= 2 * NN) return;
    if (w < NN) {
        gat_node<2>(hcv, DX, esrc, off[w], off[w + 1], dinv, bv, ov, w, lane);
    } else {
        int n = w - NN;
        gat_node<2>(hct, DX, esrc, off[n], off[n + 1], dinv, bt, ot, n, lane);
    }
}

// output: [representation | v_rep | t_rep], each N x 128 with rows [x1|x2]
__global__ void __launch_bounds__(256)
k_final(const float* __restrict__ vx1, const float* __restrict__ vx2,
        const float* __restrict__ tx1, const float* __restrict__ tx2,
        float* __restrict__ out, int out_size) {
    int i = blockIdx.x * blockDim.x + threadIdx.x;
    if (i >= NN * DX) return;
    int n = i >> 6, c = i & 63;
    float a1 = vx1[i], a2 = vx2[i], b1 = tx1[i], b2 = tx2[i];
    size_t base = (size_t)n * 128;
    out[base + c]      = (a1 + b1) * 0.5f;
    out[base + 64 + c] = (a2 + b2) * 0.5f;
    if (out_size >= 2 * NN * 128) {
        out[(size_t)NN * 128 + base + c]      = a1;
        out[(size_t)NN * 128 + base + 64 + c] = a2;
    }
    if (out_size >= 3 * NN * 128) {
        out[(size_t)2 * NN * 128 + base + c]      = b1;
        out[(size_t)2 * NN * 128 + base + 64 + c] = b2;
    }
}

// ---------------- host side ----------------
extern "C" void kernel_launch(void* const* d_in, const int* in_sizes, int n_in,
                              void* d_out, int out_size) {
    static float* F = nullptr;
    static int*   I = nullptr;
    if (!F) {
        cudaGetSymbolAddress((void**)&F, g_farena);
        cudaGetSymbolAddress((void**)&I, g_iarena);
    }

    // float arena
    float* x_v  = F;                       // NN*256
    float* hc_v = F + 7680000;             // NN*256
    float* h_v  = F + 15360000;            // NN*256
    float* x_t  = F + 23040000;            // NN*100
    float* hc_t = F + 26040000;            // NN*100
    float* h_t  = F + 29040000;            // NN*100
    float* tl_v = F + 32040000;            // NN*64
    float* tl_t = F + 33960000;            // NN*64
    float* vx1  = F + 35880000;
    float* vx2  = F + 37800000;
    float* tx1  = F + 39720000;
    float* tx2  = F + 41640000;
    float* dinv = F + 43560000;            // NN

    // int arena (cnt and degs adjacent for one zero pass)
    int* src   = I;
    int* dst   = I + NE;
    int* order = I + 2 * NE;
    int* esrc  = I + 3 * NE;
    int* cnt   = I + 4 * NE;               // NN+1
    int* degs  = cnt + (NN + 1);           // NN
    int* off   = degs + NN;                // NN+1
    int* cur   = off + (NN + 1);           // NN
    int* is64  = cur + NN;

    const float* feat  = (const float*)d_in[0];
    const void*  ei    = d_in[1];
    const float* idemb = (const float*)d_in[2];
    void* const* PV = d_in + 3;
    void* const* PT = d_in + 17;

#define PW(P, i) ((const float*)P[i])

    dim3 blk(256);
    int gy = (NN + 127) / 128;
    int warp2_grid = (2 * NN * 32 + 255) / 256;
    int gat_grid = (2 * NN * 32 + 127) / 128;

    // --- early independent stages first (profiler slot lands on a GEMM) ---
    k_zero_i<<<(2 * NN + 256) / 256, 256>>>(cnt, 2 * NN + 1);
    k_detect<<<1, 1>>>(ei, is64);
    k_convert_hist<<<(NE + 255) / 256, 256>>>(ei, src, dst, cnt, degs, is64);

    // S1: mlp GEMM (v: 192-col feat slice K=128 -> 256; t: K=64 -> 100)
    {
        GP g0 = {feat, PW(PV, 0), x_v, nullptr, nullptr, nullptr, FDIM, LV, LV, 128, LV};
        GP g1 = {feat + 128, PW(PT, 0), x_t, nullptr, nullptr, nullptr, FDIM, LT, LT, 64, LT};
        k_gemm2<0><<<dim3(4, gy, 2), blk>>>(g0, g1, nullptr);
    }
    // S2: tanh + l2norm
    k_tanh2<<<warp2_grid, 256>>>(x_v, PW(PV, 1), x_t, PW(PT, 1));
    // S3: c1 GEMM
    {
        GP g0 = {x_v, PW(PV, 2), hc_v, nullptr, nullptr, nullptr, LV, LV, LV, LV, LV};
        GP g1 = {x_t, PW(PT, 2), hc_t, nullptr, nullptr, nullptr, LT, LT, LT, LT, LT};
        k_gemm2<0><<<dim3(4, gy, 2), blk>>>(g0, g1, nullptr);
    }

    // --- rest of graph build ---
    k_scan<<<1, 1024>>>(cnt, off, cur, degs, dinv);
    k_fill<<<(NE + 255) / 256, 256>>>(dst, cur, order);
    k_sortseg_gather<<<(NN + 255) / 256, 256>>>(off, order, src, esrc);

    // S4: GAT layer 1
    k_gat1<<<gat_grid, 128>>>(hc_v, hc_t, esrc, off, dinv, PW(PV, 3), PW(PT, 3), h_v, h_t);

    // S5: l1 GEMM
    {
        GP g0 = {x_v, PW(PV, 4), tl_v, nullptr, nullptr, nullptr, LV, DX, DX, LV, DX};
        GP g1 = {x_t, PW(PT, 4), tl_t, nullptr, nullptr, nullptr, LT, DX, DX, LT, DX};
        k_gemm2<0><<<dim3(1, gy, 2), blk>>>(g0, g1, nullptr);
    }
    // S6: g1 GEMM + combine epilogue -> x1
    {
        GP g0 = {h_v, PW(PV, 6), vx1, tl_v, PW(PV, 5), PW(PV, 7), LV, DX, DX, LV, DX};
        GP g1 = {h_t, PW(PT, 6), tx1, tl_t, PW(PT, 5), PW(PT, 7), LT, DX, DX, LT, DX};
        k_gemm2<1><<<dim3(1, gy, 2), blk>>>(g0, g1, idemb);
    }
    // S7: c2 GEMM
    {
        GP g0 = {vx1, PW(PV, 8), hc_v, nullptr, nullptr, nullptr, DX, DX, DX, DX, DX};
        GP g1 = {tx1, PW(PT, 8), hc_t, nullptr, nullptr, nullptr, DX, DX, DX, DX, DX};
        k_gemm2<0><<<dim3(1, gy, 2), blk>>>(g0, g1, nullptr);
    }
    // S8: GAT layer 2
    k_gat2<<<gat_grid, 128>>>(hc_v, hc_t, esrc, off, dinv, PW(PV, 9), PW(PT, 9), h_v, h_t);

    // S9: l2 GEMM
    {
        GP g0 = {vx1, PW(PV, 10), tl_v, nullptr, nullptr, nullptr, DX, DX, DX, DX, DX};
        GP g1 = {tx1, PW(PT, 10), tl_t, nullptr, nullptr, nullptr, DX, DX, DX, DX, DX};
        k_gemm2<0><<<dim3(1, gy, 2), blk>>>(g0, g1, nullptr);
    }
    // S10: g2 GEMM + combine epilogue -> x2
    {
        GP g0 = {h_v, PW(PV, 12), vx2, tl_v, PW(PV, 11), PW(PV, 13), DX, DX, DX, DX, DX};
        GP g1 = {h_t, PW(PT, 12), tx2, tl_t, PW(PT, 11), PW(PT, 13), DX, DX, DX, DX, DX};
        k_gemm2<1><<<dim3(1, gy, 2), blk>>>(g0, g1, idemb);
    }

    // outputs
    k_final<<<(NN * DX + 255) / 256, 256>>>(vx1, vx2, tx1, tx2, (float*)d_out, out_size);
#undef PW
}

// round 5
// speedup vs baseline: 1.5945x; 1.0115x over previous
#include <cuda_runtime.h>
#include <math.h>
#include <stdint.h>

#define NN 30000
#define NE 480000
#define FDIM 192
#define DX 64
#define LV 256
#define LT 100

// ---------------- scratch arenas (no allocs allowed) ----------------
__device__ float g_farena[44000000];
__device__ int   g_iarena[2100000];

// ---------------- graph build ----------------
__global__ void k_detect(const void* ei, int* is64) {
    const int* p = (const int*)ei;
    int zeros = 0;
    for (int i = 1; i < 256; i += 2) if (p[i] == 0) zeros++;
    *is64 = (zeros >= 120) ? 1 : 0;
}

__global__ void k_zero_i(int* a, int n) {
    int i = blockIdx.x * blockDim.x + threadIdx.x;
    if (i < n) a[i] = 0;
}

__global__ void k_convert_hist(const void* ei, int* src, int* dst,
                               int* cnt, int* degs, const int* is64) {
    int e = blockIdx.x * blockDim.x + threadIdx.x;
    if (e >= NE) return;
    int s, d;
    if (*is64) {
        const long long* p = (const long long*)ei;
        s = (int)p[e];
        d = (int)p[NE + e];
    } else {
        const int* p = (const int*)ei;
        s = p[e];
        d = p[NE + e];
    }
    src[e] = s;
    dst[e] = d;
    atomicAdd(&cnt[d], 1);
    atomicAdd(&degs[s], 1);
}

// 1024 threads, 30 counts per thread serially + warp-shuffle hierarchical scan
__global__ void __launch_bounds__(1024)
k_scan(const int* __restrict__ cnt, int* __restrict__ off, int* __restrict__ cur,
       const int* __restrict__ degs, float* __restrict__ dinv) {
    const int CH = 30;
    int t = threadIdx.x;
    int base = t * CH;
    int s = 0;
#pragma unroll 5
    for (int i = 0; i < CH; i++) {
        int idx = base + i;
        if (idx < NN) s += cnt[idx];
    }
    int lane = t & 31, wid = t >> 5;
    int v = s;
#pragma unroll
    for (int o = 1; o < 32; o <<= 1) {
        int u = __shfl_up_sync(~0u, v, o);
        if (lane >= o) v += u;
    }
    __shared__ int wt[32];
    if (lane == 31) wt[wid] = v;
    __syncthreads();
    if (wid == 0) {
        int w = wt[lane];
#pragma unroll
        for (int o = 1; o < 32; o <<= 1) {
            int u = __shfl_up_sync(~0u, w, o);
            if (lane >= o) w += u;
        }
        wt[lane] = w;
    }
    __syncthreads();
    int pre = v - s + (wid ? wt[wid - 1] : 0);
    int run = pre;
#pragma unroll 5
    for (int i = 0; i < CH; i++) {
        int idx = base + i;
        if (idx < NN) {
            off[idx] = run;
            cur[idx] = run;
            int dg = degs[idx];
            dinv[idx] = (dg > 0) ? rsqrtf((float)dg) : 0.f;
            run += cnt[idx];
        }
    }
    if (t == 1023) off[NN] = run;
}

__global__ void k_fill(const int* dst, int* cur, int* order) {
    int e = blockIdx.x * blockDim.x + threadIdx.x;
    if (e >= NE) return;
    int p = atomicAdd(&cur[dst[e]], 1);
    order[p] = e;
}

__global__ void k_sortseg_gather(const int* __restrict__ off, int* __restrict__ order,
                                 const int* __restrict__ src, int* __restrict__ esrc) {
    int n = blockIdx.x * blockDim.x + threadIdx.x;
    if (n >= NN) return;
    int b = off[n], e = off[n + 1];
    for (int i = b + 1; i < e; i++) {
        int v = order[i];
        int j = i - 1;
        while (j >= b && order[j] > v) { order[j + 1] = order[j]; j--; }
        order[j + 1] = v;
    }
    for (int p = b; p < e; p++) esrc[p] = src[order[p]];
}

// ---------------- combined two-branch GEMM ----------------
struct GP {
    const float* A;
    const float* B;
    float* C;
    const float* tl;
    const float* lb;
    const float* gb;
    int lda, ldb, ldc, K, M;
};

// BM=128, BN=64, BK=16, 256 threads, 8x4 per thread, double-buffered smem.
// EPI==1: C := lrelu( acc + gb[c] + lrelu(tl+lb) + id )  (M<=64, ldc=64)
template <int EPI>
__global__ void __launch_bounds__(256)
k_gemm2(GP g0, GP g1, const float* __restrict__ id) {
    GP g = (blockIdx.z == 0) ? g0 : g1;
    int bcol = blockIdx.x * 64;
    if (bcol >= g.M) return;
    __shared__ float sA[2][16][128];
    __shared__ float sB[2][16][64];
    int tid = threadIdx.x;
    int tx = tid & 15, ty = tid >> 4;
    int brow = blockIdx.y * 128;
    const int K = g.K, M = g.M;

    // per-thread load coordinates
    const int ar0 = tid >> 2, akq = (tid & 3) * 4;          // A it=0: row, k-quad
    const int ar1 = (tid + 256) >> 2;                       // A it=1 row (same akq)
    const int bkr = tid >> 4, bcq = (tid & 15) * 4;         // B: k-row, col-quad

    float4 pA0, pA1, pB;

#define LOAD_TILE(k0)                                                          \
    do {                                                                       \
        pA0 = make_float4(0.f, 0.f, 0.f, 0.f);                                 \
        pA1 = make_float4(0.f, 0.f, 0.f, 0.f);                                 \
        pB  = make_float4(0.f, 0.f, 0.f, 0.f);                                 \
        if (brow + ar0 < NN) {                                                 \
            const float* ap = g.A + (size_t)(brow + ar0) * g.lda + (k0) + akq; \
            if ((k0) + akq + 3 < K) pA0 = *(const float4*)ap;                  \
            else {                                                             \
                if ((k0) + akq + 0 < K) pA0.x = ap[0];                         \
                if ((k0) + akq + 1 < K) pA0.y = ap[1];                         \
                if ((k0) + akq + 2 < K) pA0.z = ap[2];                         \
                if ((k0) + akq + 3 < K) pA0.w = ap[3];                         \
            }                                                                  \
        }                                                                      \
        if (brow + ar1 < NN) {                                                 \
            const float* ap = g.A + (size_t)(brow + ar1) * g.lda + (k0) + akq; \
            if ((k0) + akq + 3 < K) pA1 = *(const float4*)ap;                  \
            else {                                                             \
                if ((k0) + akq + 0 < K) pA1.x = ap[0];                         \
                if ((k0) + akq + 1 < K) pA1.y = ap[1];                         \
                if ((k0) + akq + 2 < K) pA1.z = ap[2];                         \
                if ((k0) + akq + 3 < K) pA1.w = ap[3];                         \
            }                                                                  \
        }                                                                      \
        if ((k0) + bkr < K) {                                                  \
            const float* bp = g.B + (size_t)((k0) + bkr) * g.ldb + bcol + bcq; \
            if (bcol + bcq + 3 < M) pB = *(const float4*)bp;                   \
            else {                                                             \
                if (bcol + bcq + 0 < M) pB.x = bp[0];                          \
                if (bcol + bcq + 1 < M) pB.y = bp[1];                          \
                if (bcol + bcq + 2 < M) pB.z = bp[2];                          \
                if (bcol + bcq + 3 < M) pB.w = bp[3];                          \
            }                                                                  \
        }                                                                      \
    } while (0)

#define STORE_TILE(buf)                                                        \
    do {                                                                       \
        sA[buf][akq + 0][ar0] = pA0.x;                                         \
        sA[buf][akq + 1][ar0] = pA0.y;                                         \
        sA[buf][akq + 2][ar0] = pA0.z;                                         \
        sA[buf][akq + 3][ar0] = pA0.w;                                         \
        sA[buf][akq + 0][ar1] = pA1.x;                                         \
        sA[buf][akq + 1][ar1] = pA1.y;                                         \
        sA[buf][akq + 2][ar1] = pA1.z;                                         \
        sA[buf][akq + 3][ar1] = pA1.w;                                         \
        *(float4*)&sB[buf][bkr][bcq] = pB;                                     \
    } while (0)

    float acc[8][4] = {};
    LOAD_TILE(0);
    STORE_TILE(0);
    __syncthreads();
    int buf = 0;

    for (int k0 = 0; k0 < K; k0 += 16) {
        int nk = k0 + 16;
        if (nk < K) LOAD_TILE(nk);
#pragma unroll
        for (int kk = 0; kk < 16; kk++) {
            float4 a0 = *(const float4*)&sA[buf][kk][ty * 8];
            float4 a1 = *(const float4*)&sA[buf][kk][ty * 8 + 4];
            float4 b  = *(const float4*)&sB[buf][kk][tx * 4];
            float a[8] = {a0.x, a0.y, a0.z, a0.w, a1.x, a1.y, a1.z, a1.w};
            float bb[4] = {b.x, b.y, b.z, b.w};
#pragma unroll
            for (int i = 0; i < 8; i++)
#pragma unroll
                for (int j = 0; j < 4; j++)
                    acc[i][j] += a[i] * bb[j];
        }
        if (nk < K) {
            STORE_TILE(buf ^ 1);
            __syncthreads();
            buf ^= 1;
        }
    }
#undef LOAD_TILE
#undef STORE_TILE

#pragma unroll
    for (int i = 0; i < 8; i++) {
        int r = brow + ty * 8 + i;
        if (r >= NN) continue;
#pragma unroll
        for (int j = 0; j < 4; j++) {
            int c = bcol + tx * 4 + j;
            if (c >= M) continue;
            if (EPI == 0) {
                g.C[(size_t)r * g.ldc + c] = acc[i][j];
            } else {
                size_t lin = (size_t)r * 64 + c;
                float xh = g.tl[lin] + g.lb[c];
                xh = (xh > 0.f) ? xh : 0.01f * xh;
                xh += id[lin];
                float v = acc[i][j] + g.gb[c] + xh;
                g.C[lin] = (v > 0.f) ? v : 0.01f * v;
            }
        }
    }
}

// ---------------- combined tanh + l2norm (both branches) ----------------
__global__ void __launch_bounds__(256)
k_tanh2(float* __restrict__ xv, const float* __restrict__ bv,
        float* __restrict__ xt, const float* __restrict__ bt) {
    int w = (blockIdx.x * blockDim.x + threadIdx.x) >> 5;
    int lane = threadIdx.x & 31;
    if (w >= 2 * NN) return;
    float* row;
    const float* b;
    int dim;
    if (w < NN) { row = xv + (size_t)w * LV; b = bv; dim = LV; }
    else        { row = xt + (size_t)(w - NN) * LT; b = bt; dim = LT; }
    float v[8];
    float ss = 0.f;
#pragma unroll
    for (int j = 0; j < 8; j++) {
        v[j] = 0.f;
        int c = lane + 32 * j;
        if (c < dim) {
            float t = tanhf(row[c] + b[c]);
            v[j] = t;
            ss += t * t;
        }
    }
#pragma unroll
    for (int o = 16; o; o >>= 1) ss += __shfl_xor_sync(~0u, ss, o);
    float sc = 1.f / fmaxf(sqrtf(ss), 1e-12f);
#pragma unroll
    for (int j = 0; j < 8; j++) {
        int c = lane + 32 * j;
        if (c < dim) row[c] = v[j] * sc;
    }
}

// ---------------- vector helpers ----------------
template <int VEC>
__device__ __forceinline__ void ldrow(const float* __restrict__ p, float* v) {
    if (VEC == 8) {
        float4 a = *(const float4*)p;
        float4 b = *(const float4*)(p + 4);
        v[0] = a.x; v[1] = a.y; v[2] = a.z; v[3] = a.w;
        v[4] = b.x; v[5] = b.y; v[6] = b.z; v[7] = b.w;
    } else if (VEC == 4) {
        float4 a = *(const float4*)p;
        v[0] = a.x; v[1] = a.y; v[2] = a.z; v[3] = a.w;
    } else {
        float2 a = *(const float2*)p;
        v[0] = a.x; v[1] = a.y;
    }
}

template <int VEC>
__device__ __forceinline__ void strow(float* __restrict__ p, const float* v) {
    if (VEC == 8) {
        *(float4*)p       = make_float4(v[0], v[1], v[2], v[3]);
        *(float4*)(p + 4) = make_float4(v[4], v[5], v[6], v[7]);
    } else if (VEC == 4) {
        *(float4*)p = make_float4(v[0], v[1], v[2], v[3]);
    } else {
        *(float2*)p = make_float2(v[0], v[1]);
    }
}

// ---------------- GAT (single-pass online softmax) ----------------
template <int VEC>
__device__ __forceinline__ void gat_update(const float* v, float di,
                                           const float (&hd)[VEC], float (&acc)[VEC],
                                           float& m, float& denom) {
    float d = 0.f;
#pragma unroll
    for (int j = 0; j < VEC; j++) {
        float lr = (v[j] > 0.f) ? v[j] : 0.01f * v[j];
        d += hd[j] * lr;
    }
#pragma unroll
    for (int o = 16; o; o >>= 1) d += __shfl_xor_sync(~0u, d, o);
    float t = d * di;
    float gate = 1.f / (1.f + __expf(-t));
    float lg = d * gate;
    if (lg > m) {
        float sc = __expf(m - lg);
        denom *= sc;
#pragma unroll
        for (int j = 0; j < VEC; j++) acc[j] *= sc;
        m = lg;
    }
    float w = __expf(lg - m);
    denom += w;
#pragma unroll
    for (int j = 0; j < VEC; j++) acc[j] += w * v[j];
}

template <int VEC>
__device__ __forceinline__ void gat_node(const float* __restrict__ hc, int dim,
                                         const int* __restrict__ esrc, int b0, int b1,
                                         const float* __restrict__ dinv,
                                         const float* __restrict__ bias,
                                         float* __restrict__ out, int n, int lane) {
    int c0 = lane * VEC;
    bool valid = c0 < dim;
    float hd[VEC];
#pragma unroll
    for (int j = 0; j < VEC; j++) hd[j] = 0.f;
    if (valid) ldrow<VEC>(hc + (size_t)n * dim + c0, hd);

    float m = -1e30f, denom = 0.f;
    float acc[VEC];
#pragma unroll
    for (int j = 0; j < VEC; j++) acc[j] = 0.f;

    int p = b0;
    for (; p + 3 < b1; p += 4) {
        int s[4];
        float di[4];
        float v[4][VEC];
#pragma unroll
        for (int q = 0; q < 4; q++) s[q] = esrc[p + q];
#pragma unroll
        for (int q = 0; q < 4; q++) di[q] = dinv[s[q]];
#pragma unroll
        for (int q = 0; q < 4; q++) {
#pragma unroll
            for (int j = 0; j < VEC; j++) v[q][j] = 0.f;
            if (valid) ldrow<VEC>(hc + (size_t)s[q] * dim + c0, v[q]);
        }
#pragma unroll
        for (int q = 0; q < 4; q++)
            gat_update<VEC>(v[q], di[q], hd, acc, m, denom);
    }
    for (; p < b1; p++) {
        int s = esrc[p];
        float di = dinv[s];
        float v[VEC];
#pragma unroll
        for (int j = 0; j < VEC; j++) v[j] = 0.f;
        if (valid) ldrow<VEC>(hc + (size_t)s * dim + c0, v);
        gat_update<VEC>(v, di, hd, acc, m, denom);
    }

    float inv = 1.f / (denom + 1e-16f);
    float val[VEC];
    float ss = 0.f;
#pragma unroll
    for (int j = 0; j < VEC; j++) {
        val[j] = 0.f;
        if (valid) {
            float v = acc[j] * inv + bias[c0 + j];
            val[j] = v;
            ss += v * v;
        }
    }
#pragma unroll
    for (int o = 16; o; o >>= 1) ss += __shfl_xor_sync(~0u, ss, o);
    float sc = 1.f / fmaxf(sqrtf(ss), 1e-12f);
    if (valid) {
        float res[VEC];
#pragma unroll
        for (int j = 0; j < VEC; j++) {
            float v = val[j] * sc;
            res[j] = (v > 0.f) ? v : 0.01f * v;
        }
        strow<VEC>(out + (size_t)n * dim + c0, res);
    }
}

// layer 1: v dim=256 (VEC=8), t dim=100 (VEC=4)
__global__ void __launch_bounds__(128)
k_gat1(const float* __restrict__ hcv, const float* __restrict__ hct,
       const int* __restrict__ esrc, const int* __restrict__ off,
       const float* __restrict__ dinv,
       const float* __restrict__ bv, const float* __restrict__ bt,
       float* __restrict__ ov, float* __restrict__ ot) {
    int w = (blockIdx.x * blockDim.x + threadIdx.x) >> 5;
    int lane = threadIdx.x & 31;
    if (w >= 2 * NN) return;
    if (w < NN) {
        gat_node<8>(hcv, LV, esrc, off[w], off[w + 1], dinv, bv, ov, w, lane);
    } else {
        int n = w - NN;
        gat_node<4>(hct, LT, esrc, off[n], off[n + 1], dinv, bt, ot, n, lane);
    }
}

// layer 2: both branches dim=64 (VEC=2)
__global__ void __launch_bounds__(128)
k_gat2(const float* __restrict__ hcv, const float* __restrict__ hct,
       const int* __restrict__ esrc, const int* __restrict__ off,
       const float* __restrict__ dinv,
       const float* __restrict__ bv, const float* __restrict__ bt,
       float* __restrict__ ov, float* __restrict__ ot) {
    int w = (blockIdx.x * blockDim.x + threadIdx.x) >> 5;
    int lane = threadIdx.x & 31;
    if (w >= 2 * NN) return;
    if (w < NN) {
        gat_node<2>(hcv, DX, esrc, off[w], off[w + 1], dinv, bv, ov, w, lane);
    } else {
        int n = w - NN;
        gat_node<2>(hct, DX, esrc, off[n], off[n + 1], dinv, bt, ot, n, lane);
    }
}

// output: [representation | v_rep | t_rep], each N x 128 with rows [x1|x2]
__global__ void __launch_bounds__(256)
k_final(const float* __restrict__ vx1, const float* __restrict__ vx2,
        const float* __restrict__ tx1, const float* __restrict__ tx2,
        float* __restrict__ out, int out_size) {
    int i = blockIdx.x * blockDim.x + threadIdx.x;
    if (i >= NN * DX) return;
    int n = i >> 6, c = i & 63;
    float a1 = vx1[i], a2 = vx2[i], b1 = tx1[i], b2 = tx2[i];
    size_t base = (size_t)n * 128;
    out[base + c]      = (a1 + b1) * 0.5f;
    out[base + 64 + c] = (a2 + b2) * 0.5f;
    if (out_size >= 2 * NN * 128) {
        out[(size_t)NN * 128 + base + c]      = a1;
        out[(size_t)NN * 128 + base + 64 + c] = a2;
    }
    if (out_size >= 3 * NN * 128) {
        out[(size_t)2 * NN * 128 + base + c]      = b1;
        out[(size_t)2 * NN * 128 + base + 64 + c] = b2;
    }
}

// ---------------- host side ----------------
extern "C" void kernel_launch(void* const* d_in, const int* in_sizes, int n_in,
                              void* d_out, int out_size) {
    static float* F = nullptr;
    static int*   I = nullptr;
    if (!F) {
        cudaGetSymbolAddress((void**)&F, g_farena);
        cudaGetSymbolAddress((void**)&I, g_iarena);
    }

    // float arena
    float* x_v  = F;
    float* hc_v = F + 7680000;
    float* h_v  = F + 15360000;
    float* x_t  = F + 23040000;
    float* hc_t = F + 26040000;
    float* h_t  = F + 29040000;
    float* tl_v = F + 32040000;
    float* tl_t = F + 33960000;
    float* vx1  = F + 35880000;
    float* vx2  = F + 37800000;
    float* tx1  = F + 39720000;
    float* tx2  = F + 41640000;
    float* dinv = F + 43560000;

    // int arena
    int* src   = I;
    int* dst   = I + NE;
    int* order = I + 2 * NE;
    int* esrc  = I + 3 * NE;
    int* cnt   = I + 4 * NE;
    int* degs  = cnt + (NN + 1);
    int* off   = degs + NN;
    int* cur   = off + (NN + 1);
    int* is64  = cur + NN;

    const float* feat  = (const float*)d_in[0];
    const void*  ei    = d_in[1];
    const float* idemb = (const float*)d_in[2];
    void* const* PV = d_in + 3;
    void* const* PT = d_in + 17;

#define PW(P, i) ((const float*)P[i])

    dim3 blk(256);
    int gy = (NN + 127) / 128;
    int warp2_grid = (2 * NN * 32 + 255) / 256;
    int gat_grid = (2 * NN * 32 + 127) / 128;

    k_zero_i<<<(2 * NN + 256) / 256, 256>>>(cnt, 2 * NN + 1);
    k_detect<<<1, 1>>>(ei, is64);
    k_convert_hist<<<(NE + 255) / 256, 256>>>(ei, src, dst, cnt, degs, is64);

    // S1: mlp GEMM
    {
        GP g0 = {feat, PW(PV, 0), x_v, nullptr, nullptr, nullptr, FDIM, LV, LV, 128, LV};
        GP g1 = {feat + 128, PW(PT, 0), x_t, nullptr, nullptr, nullptr, FDIM, LT, LT, 64, LT};
        k_gemm2<0><<<dim3(4, gy, 2), blk>>>(g0, g1, nullptr);
    }
    // S2: tanh + l2norm
    k_tanh2<<<warp2_grid, 256>>>(x_v, PW(PV, 1), x_t, PW(PT, 1));
    // S3: c1 GEMM
    {
        GP g0 = {x_v, PW(PV, 2), hc_v, nullptr, nullptr, nullptr, LV, LV, LV, LV, LV};
        GP g1 = {x_t, PW(PT, 2), hc_t, nullptr, nullptr, nullptr, LT, LT, LT, LT, LT};
        k_gemm2<0><<<dim3(4, gy, 2), blk>>>(g0, g1, nullptr);
    }

    // rest of graph build
    k_scan<<<1, 1024>>>(cnt, off, cur, degs, dinv);
    k_fill<<<(NE + 255) / 256, 256>>>(dst, cur, order);
    k_sortseg_gather<<<(NN + 255) / 256, 256>>>(off, order, src, esrc);

    // S4: GAT layer 1
    k_gat1<<<gat_grid, 128>>>(hc_v, hc_t, esrc, off, dinv, PW(PV, 3), PW(PT, 3), h_v, h_t);

    // S5: l1 GEMM
    {
        GP g0 = {x_v, PW(PV, 4), tl_v, nullptr, nullptr, nullptr, LV, DX, DX, LV, DX};
        GP g1 = {x_t, PW(PT, 4), tl_t, nullptr, nullptr, nullptr, LT, DX, DX, LT, DX};
        k_gemm2<0><<<dim3(1, gy, 2), blk>>>(g0, g1, nullptr);
    }
    // S6: g1 GEMM + combine epilogue -> x1
    {
        GP g0 = {h_v, PW(PV, 6), vx1, tl_v, PW(PV, 5), PW(PV, 7), LV, DX, DX, LV, DX};
        GP g1 = {h_t, PW(PT, 6), tx1, tl_t, PW(PT, 5), PW(PT, 7), LT, DX, DX, LT, DX};
        k_gemm2<1><<<dim3(1, gy, 2), blk>>>(g0, g1, idemb);
    }
    // S7: c2 GEMM
    {
        GP g0 = {vx1, PW(PV, 8), hc_v, nullptr, nullptr, nullptr, DX, DX, DX, DX, DX};
        GP g1 = {tx1, PW(PT, 8), hc_t, nullptr, nullptr, nullptr, DX, DX, DX, DX, DX};
        k_gemm2<0><<<dim3(1, gy, 2), blk>>>(g0, g1, nullptr);
    }
    // S8: GAT layer 2
    k_gat2<<<gat_grid, 128>>>(hc_v, hc_t, esrc, off, dinv, PW(PV, 9), PW(PT, 9), h_v, h_t);

    // S9: l2 GEMM
    {
        GP g0 = {vx1, PW(PV, 10), tl_v, nullptr, nullptr, nullptr, DX, DX, DX, DX, DX};
        GP g1 = {tx1, PW(PT, 10), tl_t, nullptr, nullptr, nullptr, DX, DX, DX, DX, DX};
        k_gemm2<0><<<dim3(1, gy, 2), blk>>>(g0, g1, nullptr);
    }
    // S10: g2 GEMM + combine epilogue -> x2
    {
        GP g0 = {h_v, PW(PV, 12), vx2, tl_v, PW(PV, 11), PW(PV, 13), DX, DX, DX, DX, DX};
        GP g1 = {h_t, PW(PT, 12), tx2, tl_t, PW(PT, 11), PW(PT, 13), DX, DX, DX, DX, DX};
        k_gemm2<1><<<dim3(1, gy, 2), blk>>>(g0, g1, idemb);
    }

    k_final<<<(NN * DX + 255) / 256, 256>>>(vx1, vx2, tx1, tx2, (float*)d_out, out_size);
#undef PW
}